// round 15
// baseline (speedup 1.0000x reference)
#include <cuda_runtime.h>
#include <cuda_bf16.h>
#include <math.h>
#include <stdint.h>

#define BATCH 32
#define TLEN  4096
#define HCH   256
#define NPOS  (BATCH*TLEN)      // 131072
#define LLAYER 4
#define OUTCH 58
#define OPAD  64

// ---------------- scratch ----------------
__device__ float g_hA[NPOS*HCH];              // ping-pong hidden buffers
__device__ float g_hB[NPOS*HCH];
__device__ float g_wt[LLAYER*HCH*HCH];        // tf32 weights, chunk-tiled swizzled
__device__ float g_p[NPOS*OPAD];
__device__ __nv_bfloat16 g_pwh[4*OPAD*OPAD];  // proj weights bf16 hi/lo swizzled
__device__ __nv_bfloat16 g_pwl[4*OPAD*OPAD];
__device__ float g_pb[OPAD];
__device__ float g_lad[BATCH*2*TLEN];

// ---------------- helpers ----------------
__device__ __forceinline__ uint32_t smem_u32(const void* p){
  uint32_t a;
  asm("{ .reg .u64 t; cvta.to.shared.u64 t, %1; cvt.u32.u64 %0, t; }" : "=r"(a) : "l"(p));
  return a;
}
__device__ __forceinline__ void ldsm4(unsigned &r0, unsigned &r1, unsigned &r2, unsigned &r3, uint32_t a){
  asm volatile("ldmatrix.sync.aligned.m8n8.x4.shared.b16 {%0,%1,%2,%3}, [%4];"
    : "=r"(r0),"=r"(r1),"=r"(r2),"=r"(r3) : "r"(a));
}
__device__ __forceinline__ void mma_tf32(float* d, const unsigned* a, unsigned b0, unsigned b1){
  asm volatile("mma.sync.aligned.m16n8k8.row.col.f32.tf32.tf32.f32 "
    "{%0,%1,%2,%3}, {%4,%5,%6,%7}, {%8,%9}, {%0,%1,%2,%3};"
    : "+f"(d[0]),"+f"(d[1]),"+f"(d[2]),"+f"(d[3])
    : "r"(a[0]),"r"(a[1]),"r"(a[2]),"r"(a[3]),"r"(b0),"r"(b1));
}
__device__ __forceinline__ void mma_bf16(float* d, const unsigned* a, unsigned b0, unsigned b1){
  asm volatile("mma.sync.aligned.m16n8k16.row.col.f32.bf16.bf16.f32 "
    "{%0,%1,%2,%3}, {%4,%5,%6,%7}, {%8,%9}, {%0,%1,%2,%3};"
    : "+f"(d[0]),"+f"(d[1]),"+f"(d[2]),"+f"(d[3])
    : "r"(a[0]),"r"(a[1]),"r"(a[2]),"r"(a[3]),"r"(b0),"r"(b1));
}
__device__ __forceinline__ float tf32_rna(float x){
  uint32_t r;
  asm("cvt.rna.tf32.f32 %0, %1;" : "=r"(r) : "f"(x));
  return __uint_as_float(r);
}
__device__ __forceinline__ float gelu_exact(float x){
  return 0.5f*x*(1.f+erff(x*0.70710678118654752f));
}
__device__ __forceinline__ float softplusf(float x){
  return (x > 20.f) ? x : log1pf(expf(x));
}

#define MBAR_INIT(mb, c)  asm volatile("mbarrier.init.shared.b64 [%0], %1;" :: "r"(mb), "r"((uint32_t)(c)) : "memory")
#define MBAR_EXPECT_TX(mb, tx) asm volatile("mbarrier.arrive.expect_tx.shared.b64 _, [%0], %1;" :: "r"(mb), "r"((uint32_t)(tx)) : "memory")
#define MBAR_WAIT(mb, par) do {                                                   \
  uint32_t _m = (mb); uint32_t _p = (par); uint32_t _d;                           \
  asm volatile("{\n\t.reg .pred p;\n\t"                                           \
    "mbarrier.try_wait.parity.acquire.cta.shared::cta.b64 p, [%1], %2;\n\t"       \
    "selp.b32 %0, 1, 0, p;\n\t}" : "=r"(_d) : "r"(_m), "r"(_p) : "memory");       \
  if (!_d) {                                                                      \
    asm volatile("{\n\t.reg .pred P1;\n\t"                                        \
      "W_%=:\n\t"                                                                 \
      "mbarrier.try_wait.parity.acquire.cta.shared::cta.b64 P1, [%0], %1, 0x989680;\n\t" \
      "@P1 bra.uni D_%=;\n\t"                                                     \
      "bra.uni W_%=;\n\t"                                                         \
      "D_%=:\n\t}" :: "r"(_m), "r"(_p) : "memory");                               \
  }                                                                               \
} while(0)

__device__ __forceinline__ void bulk_g2s(uint32_t dst, const void* src, uint32_t bytes, uint32_t mbar){
  asm volatile("cp.async.bulk.shared::cluster.global.mbarrier::complete_tx::bytes [%0], [%1], %2, [%3];"
    :: "r"(dst), "l"(src), "r"(bytes), "r"(mbar) : "memory");
}

// ---------------- weight prep: tf32 round + chunk-tiled swizzled layout ----------------
__global__ void k_wprep(const float* __restrict__ w){
  int i = blockIdx.x*256 + threadIdx.x;
  int layer = i >> 14;
  int j = i & 16383;
  int o = j >> 6;
  int cu = j & 63;
  int chunk = cu >> 3, uu = cu & 7;
  const float* src = w + (size_t)layer*65536 + o*256 + cu*4;
  float4 v = *(const float4*)src;
  v.x = tf32_rna(v.x); v.y = tf32_rna(v.y); v.z = tf32_rna(v.z); v.w = tf32_rna(v.w);
  float* dst = g_wt + (size_t)layer*65536 + chunk*8192 + o*32 + ((uu ^ (o & 7)) << 2);
  *(float4*)dst = v;
}

// ======== fused layer kernel: dwconv+LN1+GELU (prologue, -> smem A) ========
// ========   + tf32 GEMM (A resident, B bulk-async)                  ========
// ========   + bias+LN2+GELU+residual (epilogue, hs -> hd)           ========
// CTA: 64 positions x 256 out-ch, 256 threads, 8 warps (2M x 4N).
#define OFF_A   0                 // 64KB resident A (8 chunks x 8192)
#define OFF_B   65536             // 2 stages * 32768
#define OFF_PAR 131072            // 3 * 1024
#define OFF_RED 134144            // 64 rows * 8 floats
#define OFF_MBR 136192            // 2 mbarriers
#define GSMEM   136224

__global__ void __launch_bounds__(256, 1) k_layer(int layer, int srcsel, int dil,
                       const float* __restrict__ x,   const float* __restrict__ mask,
                       const float* __restrict__ pw,  const float* __restrict__ pb,
                       const float* __restrict__ sw,  const float* __restrict__ sb,
                       const float* __restrict__ gm1, const float* __restrict__ bt1,
                       const float* __restrict__ bias,
                       const float* __restrict__ gm2, const float* __restrict__ bt2){
  extern __shared__ char smem[];
  uint32_t sbase = smem_u32(smem);
  float* s_bias = (float*)(smem + OFF_PAR);
  float* s_g    = (float*)(smem + OFF_PAR + 1024);
  float* s_bt   = (float*)(smem + OFF_PAR + 2048);
  float* s_red  = (float*)(smem + OFF_RED);

  int tid = threadIdx.x, lane = tid & 31, w = tid >> 5;
  int n0 = blockIdx.x * 64;

  const float* hs = srcsel ? g_hB : g_hA;
  float*       hd = srcsel ? g_hA : g_hB;
  const char*  gB = (const char*)(g_wt + (size_t)layer*65536);

  s_bias[tid] = bias[tid]; s_g[tid] = gm2[tid]; s_bt[tid] = bt2[tid];
  if (tid == 0){ MBAR_INIT(sbase + OFF_MBR, 1); MBAR_INIT(sbase + OFF_MBR + 16, 1); }
  __syncthreads();

  #define ISSUE_B(q) {                                                      \
    uint32_t _mb = sbase + OFF_MBR + ((q)&1)*16;                            \
    MBAR_EXPECT_TX(_mb, 32768);                                             \
    bulk_g2s(sbase + OFF_B + ((q)&1)*32768, gB + (size_t)(q)*32768, 32768, _mb); \
  }
  if (tid == 0){ ISSUE_B(0); ISSUE_B(1); }

  // ================= prologue: dwln for own 64 rows -> smem A =================
  {
    int c = lane*8;
    float s3[24], sbv[8], gmv[8], btv[8];
    #pragma unroll
    for (int q=0;q<6;q++) *(float4*)&s3[q*4] = *(const float4*)&sw[c*3 + q*4];
    *(float4*)&sbv[0] = *(const float4*)&sb[c];  *(float4*)&sbv[4] = *(const float4*)&sb[c+4];
    *(float4*)&gmv[0] = *(const float4*)&gm1[c]; *(float4*)&gmv[4] = *(const float4*)&gm1[c+4];
    *(float4*)&btv[0] = *(const float4*)&bt1[c]; *(float4*)&btv[4] = *(const float4*)&bt1[c+4];

    float pwv[16], pbv[8];
    if (layer == 0){
      #pragma unroll
      for (int q=0;q<4;q++) *(float4*)&pwv[q*4] = *(const float4*)&pw[c*2 + q*4];
      *(float4*)&pbv[0] = *(const float4*)&pb[c]; *(float4*)&pbv[4] = *(const float4*)&pb[c+4];
    }

    for (int p=0; p<8; p++){
      int row = w*8 + p;
      int n = n0 + row;
      int t = n & (TLEN-1);
      float v[8];

      if (layer == 0){
        int b4 = (n >> 12) * 4;
        float x0c = x[b4*TLEN + t], x1c = x[(b4+1)*TLEN + t];
        float m0 = mask[n];
        bool hasL = (t >= 1), hasR = (t + 1 < TLEN);
        float x0l=0.f,x1l=0.f,ml=0.f,x0r=0.f,x1r=0.f,mr_=0.f;
        if (hasL){ x0l = x[b4*TLEN + t-1]; x1l = x[(b4+1)*TLEN + t-1]; ml = mask[n-1]; }
        if (hasR){ x0r = x[b4*TLEN + t+1]; x1r = x[(b4+1)*TLEN + t+1]; mr_ = mask[n+1]; }
        float hc[8];
        #pragma unroll
        for (int j=0;j<8;j++){
          float wa = pwv[j*2], wb = pwv[j*2+1], pbc = pbv[j];
          float h0 = fmaf(wa, x0c, fmaf(wb, x1c, pbc));
          hc[j] = h0;
          float acc = sbv[j] + s3[j*3+1]*h0*m0;
          if (hasL){ float hl = fmaf(wa, x0l, fmaf(wb, x1l, pbc)); acc += s3[j*3+0]*hl*ml; }
          if (hasR){ float hr = fmaf(wa, x0r, fmaf(wb, x1r, pbc)); acc += s3[j*3+2]*hr*mr_; }
          v[j] = acc;
        }
        // seed h_src (g_hA) for epilogue residual read
        *(float4*)&g_hA[(size_t)n*HCH + c]     = *(float4*)&hc[0];
        *(float4*)&g_hA[(size_t)n*HCH + c + 4] = *(float4*)&hc[4];
      } else {
        float m0 = mask[n];
        float hc[8];
        *(float4*)&hc[0] = *(const float4*)&hs[(size_t)n*HCH + c];
        *(float4*)&hc[4] = *(const float4*)&hs[(size_t)n*HCH + c + 4];
        #pragma unroll
        for (int j=0;j<8;j++) v[j] = sbv[j] + s3[j*3+1]*hc[j]*m0;
        if (t >= dil){
          float mm = mask[n-dil];
          float hl[8];
          *(float4*)&hl[0] = *(const float4*)&hs[(size_t)(n-dil)*HCH + c];
          *(float4*)&hl[4] = *(const float4*)&hs[(size_t)(n-dil)*HCH + c + 4];
          #pragma unroll
          for (int j=0;j<8;j++) v[j] += s3[j*3+0]*hl[j]*mm;
        }
        if (t + dil < TLEN){
          float mm = mask[n+dil];
          float hr[8];
          *(float4*)&hr[0] = *(const float4*)&hs[(size_t)(n+dil)*HCH + c];
          *(float4*)&hr[4] = *(const float4*)&hs[(size_t)(n+dil)*HCH + c + 4];
          #pragma unroll
          for (int j=0;j<8;j++) v[j] += s3[j*3+2]*hr[j]*mm;
        }
      }

      float ls = 0.f;
      #pragma unroll
      for (int j=0;j<8;j++) ls += v[j];
      #pragma unroll
      for (int o=16;o;o>>=1) ls += __shfl_xor_sync(0xffffffffu, ls, o);
      float mean = ls * (1.f/HCH);
      float sq = 0.f;
      #pragma unroll
      for (int j=0;j<8;j++){ v[j] -= mean; sq += v[j]*v[j]; }
      #pragma unroll
      for (int o=16;o;o>>=1) sq += __shfl_xor_sync(0xffffffffu, sq, o);
      float rstd = rsqrtf(sq * (1.f/HCH) + 1e-5f);

      float o_[8];
      #pragma unroll
      for (int j=0;j<8;j++){
        float yn = v[j]*rstd*gmv[j] + btv[j];
        o_[j] = tf32_rna(gelu_exact(yn));
      }
      // store swizzled into smem A: [chunk][row][32f], unit u at u^(row&7)
      int cu0 = c >> 2;
      int chunk = cu0 >> 3, uu = cu0 & 7;
      int r7 = row & 7;
      char* abase = smem + OFF_A + chunk*8192 + row*128;
      *(float4*)(abase + ((uu ^ r7) << 4))     = *(float4*)&o_[0];
      *(float4*)(abase + (((uu+1) ^ r7) << 4)) = *(float4*)&o_[4];
    }
  }
  __syncthreads();

  // ================= mainloop =================
  int warpM = w >> 2, warpN = w & 3;
  int g = lane >> 2, tig = lane & 3;
  int mat = lane >> 3, mr = lane & 7;

  float acc[2][8][4];
  #pragma unroll
  for (int mf=0;mf<2;mf++)
    #pragma unroll
    for (int nf=0;nf<8;nf++)
      #pragma unroll
      for (int k=0;k<4;k++) acc[mf][nf][k]=0.f;

  int arow_l = (mat & 1)*8 + mr;   int amh = mat >> 1;
  int brow_l = (mat >> 1)*8 + mr;  int bmh = mat & 1;
  uint32_t aBase0 = sbase + OFF_A + (uint32_t)((warpM*32 + arow_l)*128);
  uint32_t bBase0 = sbase + OFF_B + (uint32_t)((warpN*64 + brow_l)*128);

  for (int q = 0; q < 8; q++){
    MBAR_WAIT(sbase + OFF_MBR + (q&1)*16, (q>>1)&1);

    uint32_t aBase = aBase0 + q*8192;
    uint32_t bBase = bBase0 + (q&1)*32768;

    #pragma unroll
    for (int ks=0; ks<4; ks++){
      uint32_t swa = (uint32_t)(((2*ks + amh) ^ mr) << 4);
      uint32_t swb = (uint32_t)(((2*ks + bmh) ^ mr) << 4);
      unsigned afr[2][4];
      ldsm4(afr[0][0], afr[0][1], afr[0][2], afr[0][3], aBase + swa);
      ldsm4(afr[1][0], afr[1][1], afr[1][2], afr[1][3], aBase + 2048 + swa);
      unsigned bfr[8][2];
      #pragma unroll
      for (int np=0; np<4; np++){
        unsigned t0,t1,t2,t3;
        ldsm4(t0,t1,t2,t3, bBase + np*2048 + swb);
        bfr[2*np][0]=t0; bfr[2*np][1]=t1; bfr[2*np+1][0]=t2; bfr[2*np+1][1]=t3;
      }
      #pragma unroll
      for (int nf=0; nf<8; nf++){
        mma_tf32(acc[0][nf], afr[0], bfr[nf][0], bfr[nf][1]);
        mma_tf32(acc[1][nf], afr[1], bfr[nf][0], bfr[nf][1]);
      }
    }
    __syncthreads();
    if (tid == 0 && q + 2 < 8) ISSUE_B(q+2);
  }

  // ================= epilogue: bias, LN2, GELU, residual hs->hd =================
  float s[4]  = {0.f,0.f,0.f,0.f};
  float sq[4] = {0.f,0.f,0.f,0.f};
  #pragma unroll
  for (int mf=0; mf<2; mf++)
    #pragma unroll
    for (int nf=0; nf<8; nf++){
      int ch0 = warpN*64 + nf*8 + tig*2;
      float b0 = s_bias[ch0], b1 = s_bias[ch0+1];
      acc[mf][nf][0]+=b0; acc[mf][nf][1]+=b1;
      acc[mf][nf][2]+=b0; acc[mf][nf][3]+=b1;
      s [mf*2+0] += acc[mf][nf][0]+acc[mf][nf][1];
      sq[mf*2+0] += acc[mf][nf][0]*acc[mf][nf][0] + acc[mf][nf][1]*acc[mf][nf][1];
      s [mf*2+1] += acc[mf][nf][2]+acc[mf][nf][3];
      sq[mf*2+1] += acc[mf][nf][2]*acc[mf][nf][2] + acc[mf][nf][3]*acc[mf][nf][3];
    }
  #pragma unroll
  for (int sl=0; sl<4; sl++){
    s [sl] += __shfl_xor_sync(0xffffffffu, s [sl], 1);
    s [sl] += __shfl_xor_sync(0xffffffffu, s [sl], 2);
    sq[sl] += __shfl_xor_sync(0xffffffffu, sq[sl], 1);
    sq[sl] += __shfl_xor_sync(0xffffffffu, sq[sl], 2);
  }
  __syncthreads();
  if (tig == 0){
    #pragma unroll
    for (int sl=0; sl<4; sl++){
      int mf = sl >> 1, h = sl & 1;
      int row = warpM*32 + mf*16 + h*8 + g;
      s_red[row*8 + warpN*2 + 0] = s[sl];
      s_red[row*8 + warpN*2 + 1] = sq[sl];
    }
  }
  __syncthreads();

  float mean_[4], rstd_[4];
  #pragma unroll
  for (int sl=0; sl<4; sl++){
    int mf = sl >> 1, h = sl & 1;
    int row = warpM*32 + mf*16 + h*8 + g;
    float su = s_red[row*8+0]+s_red[row*8+2]+s_red[row*8+4]+s_red[row*8+6];
    float qq = s_red[row*8+1]+s_red[row*8+3]+s_red[row*8+5]+s_red[row*8+7];
    float mn = su * (1.f/HCH);
    float var = qq * (1.f/HCH) - mn*mn;
    mean_[sl] = mn;
    rstd_[sl] = rsqrtf(var + 1e-5f);
  }

  #pragma unroll
  for (int mf=0; mf<2; mf++)
    #pragma unroll
    for (int nf=0; nf<8; nf++){
      int ch0 = warpN*64 + nf*8 + tig*2;
      float g0 = s_g[ch0], g1 = s_g[ch0+1];
      float t0 = s_bt[ch0], t1 = s_bt[ch0+1];
      #pragma unroll
      for (int h=0; h<2; h++){
        int sl = mf*2 + h;
        int row = n0 + warpM*32 + mf*16 + h*8 + g;
        float v0 = (acc[mf][nf][h*2+0] - mean_[sl])*rstd_[sl]*g0 + t0;
        float v1 = (acc[mf][nf][h*2+1] - mean_[sl])*rstd_[sl]*g1 + t1;
        float2 hv = *(const float2*)&hs[(size_t)row*HCH + ch0];
        hv.x += gelu_exact(v0);
        hv.y += gelu_exact(v1);
        *(float2*)&hd[(size_t)row*HCH + ch0] = hv;
      }
    }
}

// ---------------- proj weight prep: bf16 hi/lo, chunked swizzled ----------------
__global__ void k_padw(const float* __restrict__ pjw, const float* __restrict__ pjb){
  int o = blockIdx.x, k = threadIdx.x;
  float w = (o < OUTCH) ? pjw[o*HCH + k] : 0.f;
  __nv_bfloat16 h = __float2bfloat16(w);
  __nv_bfloat16 l = __float2bfloat16(w - __bfloat162float(h));
  int chunk = k >> 6;
  int kk = k & 63;
  int uu = kk >> 3, pos = kk & 7;
  int off = chunk*4096 + o*64 + ((uu ^ (o & 7)) << 3) + pos;
  g_pwh[off] = h;
  g_pwl[off] = l;
  if (k == 0) g_pb[o] = (o < OUTCH) ? pjb[o] : 0.f;
}

// ---------------- projection: bf16 hi/lo mma, g_p = (W(h*m)+b)*m ----------------
// reads g_hA (final hidden after layer 3)
__global__ void __launch_bounds__(256) k_projmma(const float* __restrict__ mask){
  __shared__ __nv_bfloat16 sAh[64*64], sAl[64*64], sBh[64*64], sBl[64*64];
  __shared__ float s_pb[64];
  int tid = threadIdx.x, lane = tid & 31, wid = tid >> 5;
  int warpM = wid & 3, warpN = wid >> 2;
  int g = lane >> 2, tig = lane & 3;
  int mat = lane >> 3, mr = lane & 7;
  int n0 = blockIdx.x * 64;
  if (tid < 64) s_pb[tid] = g_pb[tid];

  uint32_t sah = smem_u32(sAh), sal = smem_u32(sAl);
  uint32_t sbh = smem_u32(sBh), sbl = smem_u32(sBl);

  float acc[4][4];
  #pragma unroll
  for (int nf=0;nf<4;nf++)
    #pragma unroll
    for (int k=0;k<4;k++) acc[nf][k]=0.f;

  int arow_l = (mat & 1)*8 + mr;   int amh = mat >> 1;
  int brow_l = (mat >> 1)*8 + mr;  int bmh = mat & 1;
  uint32_t aOffW = (uint32_t)((warpM*16 + arow_l)*128);
  uint32_t bOffW = (uint32_t)((warpN*32 + brow_l)*128);

  int row = tid >> 2;
  int kq  = (tid & 3) * 16;
  float m_row = mask[n0 + row];
  int r7 = row & 7;
  int u0 = (tid & 3) * 2;

  for (int chunk=0; chunk<4; chunk++){
    __syncthreads();
    {
      float hv[16];
      const float* src = &g_hA[(size_t)(n0+row)*HCH + chunk*64 + kq];
      *(float4*)&hv[0]  = *(const float4*)&src[0];
      *(float4*)&hv[4]  = *(const float4*)&src[4];
      *(float4*)&hv[8]  = *(const float4*)&src[8];
      *(float4*)&hv[12] = *(const float4*)&src[12];
      __nv_bfloat16 hi[16], lo[16];
      #pragma unroll
      for (int j=0;j<16;j++){
        float v = hv[j]*m_row;
        __nv_bfloat16 h = __float2bfloat16(v);
        hi[j] = h;
        lo[j] = __float2bfloat16(v - __bfloat162float(h));
      }
      uint32_t o0 = (uint32_t)(row*128 + ((u0 ^ r7) << 4));
      uint32_t o1 = (uint32_t)(row*128 + (((u0+1) ^ r7) << 4));
      *(uint4*)((char*)sAh + o0) = *(uint4*)&hi[0];
      *(uint4*)((char*)sAh + o1) = *(uint4*)&hi[8];
      *(uint4*)((char*)sAl + o0) = *(uint4*)&lo[0];
      *(uint4*)((char*)sAl + o1) = *(uint4*)&lo[8];
    }
    {
      const uint4* srcH = (const uint4*)&g_pwh[chunk*4096];
      const uint4* srcL = (const uint4*)&g_pwl[chunk*4096];
      ((uint4*)sBh)[tid]       = srcH[tid];
      ((uint4*)sBh)[tid + 256] = srcH[tid + 256];
      ((uint4*)sBl)[tid]       = srcL[tid];
      ((uint4*)sBl)[tid + 256] = srcL[tid + 256];
    }
    __syncthreads();

    #pragma unroll
    for (int kst=0; kst<4; kst++){
      uint32_t ua = (uint32_t)(((2*kst + amh) ^ mr) << 4);
      uint32_t ub = (uint32_t)(((2*kst + bmh) ^ mr) << 4);
      unsigned ah[4], al[4];
      ldsm4(ah[0],ah[1],ah[2],ah[3], sah + aOffW + ua);
      ldsm4(al[0],al[1],al[2],al[3], sal + aOffW + ua);
      unsigned bh[4][2], bl[4][2];
      #pragma unroll
      for (int np=0; np<2; np++){
        unsigned t0,t1,t2,t3;
        ldsm4(t0,t1,t2,t3, sbh + bOffW + np*2048 + ub);
        bh[2*np][0]=t0; bh[2*np][1]=t1; bh[2*np+1][0]=t2; bh[2*np+1][1]=t3;
        ldsm4(t0,t1,t2,t3, sbl + bOffW + np*2048 + ub);
        bl[2*np][0]=t0; bl[2*np][1]=t1; bl[2*np+1][0]=t2; bl[2*np+1][1]=t3;
      }
      #pragma unroll
      for (int nf=0; nf<4; nf++){
        mma_bf16(acc[nf], ah, bh[nf][0], bh[nf][1]);
        mma_bf16(acc[nf], ah, bl[nf][0], bl[nf][1]);
        mma_bf16(acc[nf], al, bh[nf][0], bh[nf][1]);
      }
    }
  }

  #pragma unroll
  for (int nf=0; nf<4; nf++){
    int ch0 = warpN*32 + nf*8 + tig*2;
    float b0 = s_pb[ch0], b1 = s_pb[ch0+1];
    #pragma unroll
    for (int h=0; h<2; h++){
      int r = n0 + warpM*16 + h*8 + g;
      float m = mask[r];
      float2 v;
      v.x = (acc[nf][h*2+0] + b0) * m;
      v.y = (acc[nf][h*2+1] + b1) * m;
      *(float2*)&g_p[(size_t)r*OPAD + ch0] = v;
    }
  }
}

// ---------------- rational-quadratic spline ----------------
__global__ void k_spline(const float* __restrict__ x, const float* __restrict__ mask,
                         float* __restrict__ out){
  int i = blockIdx.x*256 + threadIdx.x;
  int t = i & (TLEN-1);
  int bc = i >> 12;
  int c = bc & 1, b = bc >> 1;
  float m = mask[b*TLEN + t];
  const float* p = &g_p[(size_t)(b*TLEN + t)*OPAD + c*29];
  float x1 = x[(b*4 + 2 + c)*TLEN + t];

  out[(b*4 + c)*TLEN + t] = x[(b*4 + c)*TLEN + t] * m;

  const float scale = 0.0625f;
  float ew[10], eh[10];
  float mw = -1e30f, mh = -1e30f;
  #pragma unroll
  for (int j=0;j<10;j++){ mw = fmaxf(mw, p[j]*scale); mh = fmaxf(mh, p[10+j]*scale); }
  float sw = 0.f, sh = 0.f;
  #pragma unroll
  for (int j=0;j<10;j++){
    ew[j] = expf(p[j]*scale - mw);    sw += ew[j];
    eh[j] = expf(p[10+j]*scale - mh); sh += eh[j];
  }
  float invsw = 1.f/sw, invsh = 1.f/sh;
  float xc = fminf(fmaxf(x1, -5.f), 5.f);

  float cumw = 0.f, cumh = 0.f;
  float cwj = -5.f, chj = -5.f;
  int idx = 9;
  float in_cw = 0.f, in_w = 1.f, in_ch = 0.f, in_h = 1.f;
  bool found = false;
  #pragma unroll
  for (int j=0;j<10;j++){
    cumw += 0.001f + 0.99f*ew[j]*invsw;
    cumh += 0.001f + 0.99f*eh[j]*invsh;
    float nw = (j==9) ? 5.f : fmaf(10.f, cumw, -5.f);
    float nh = (j==9) ? 5.f : fmaf(10.f, cumh, -5.f);
    if (!found && (xc < nw || j==9)){
      found = true; idx = j;
      in_cw = cwj; in_w = nw - cwj;
      in_ch = chj; in_h = nh - chj;
    }
    cwj = nw; chj = nh;
  }
  float dk  = (idx==0) ? 1.f : 0.001f + softplusf(p[20 + idx - 1]);
  float dk1 = (idx==9) ? 1.f : 0.001f + softplusf(p[20 + idx]);
  float delta = in_h / in_w;
  float th  = (xc - in_cw) / in_w;
  float th2 = th*th;
  float t1m = th*(1.f - th);
  float num = in_h * (delta*th2 + dk*t1m);
  float den = delta + (dk + dk1 - 2.f*delta)*t1m;
  float y = in_ch + num/den;
  float omt = 1.f - th;
  float dnum = delta*delta*(dk1*th2 + 2.f*delta*t1m + dk*omt*omt);
  float lad = logf(dnum) - 2.f*logf(den);

  bool inside = (x1 >= -5.f) && (x1 <= 5.f);
  y   = inside ? y   : x1;
  lad = inside ? lad : 0.f;

  out[(b*4 + 2 + c)*TLEN + t] = y * m;
  g_lad[i] = lad * m;
}

__global__ void k_reduce(float* __restrict__ out){
  int b = blockIdx.x;
  float s = 0.f;
  for (int j = threadIdx.x; j < 2*TLEN; j += 256) s += g_lad[b*2*TLEN + j];
  __shared__ float sm[8];
  #pragma unroll
  for (int o=16;o;o>>=1) s += __shfl_xor_sync(0xffffffffu, s, o);
  if ((threadIdx.x&31)==0) sm[threadIdx.x>>5]=s;
  __syncthreads();
  if (threadIdx.x == 0){
    float r = sm[0]+sm[1]+sm[2]+sm[3]+sm[4]+sm[5]+sm[6]+sm[7];
    out[BATCH*4*TLEN + b] = r;
  }
}

extern "C" void kernel_launch(void* const* d_in, const int* in_sizes, int n_in,
                              void* d_out, int out_size){
  const float* x     = (const float*)d_in[0];
  const float* xm    = (const float*)d_in[1];
  const float* pre_w = (const float*)d_in[2];
  const float* pre_b = (const float*)d_in[3];
  const float* sep_w = (const float*)d_in[4];
  const float* sep_b = (const float*)d_in[5];
  const float* c1w   = (const float*)d_in[6];
  const float* c1b   = (const float*)d_in[7];
  const float* n1g   = (const float*)d_in[8];
  const float* n1b   = (const float*)d_in[9];
  const float* n2g   = (const float*)d_in[10];
  const float* n2b   = (const float*)d_in[11];
  const float* pjw   = (const float*)d_in[12];
  const float* pjb   = (const float*)d_in[13];
  float* out = (float*)d_out;

  static int smem_set = 0;
  if (!smem_set){
    cudaFuncSetAttribute(k_layer, cudaFuncAttributeMaxDynamicSharedMemorySize, GSMEM);
    smem_set = 1;
  }

  k_wprep<<<(LLAYER*HCH*HCH/4)/256, 256>>>(c1w);
  k_padw<<<OPAD, HCH>>>(pjw, pjb);

  int dil = 1;
  for (int i=0;i<LLAYER;i++){
    int srcsel = i & 1;   // L0: src A, dst B; L1: src B, dst A; ... L3 dst = A
    k_layer<<<NPOS/64, 256, GSMEM>>>(i, srcsel, dil, x, xm,
        pre_w, pre_b,
        sep_w + i*HCH*3, sep_b + i*HCH,
        n1g + i*HCH, n1b + i*HCH,
        c1b + i*HCH,
        n2g + i*HCH, n2b + i*HCH);
    dil *= 3;
  }

  k_projmma<<<NPOS/64, 256>>>(xm);
  k_spline<<<(BATCH*2*TLEN)/256, 256>>>(x, xm, out);
  k_reduce<<<BATCH, 256>>>(out);
}

// round 16
// speedup vs baseline: 1.0011x; 1.0011x over previous
#include <cuda_runtime.h>
#include <cuda_bf16.h>
#include <math.h>
#include <stdint.h>

#define BATCH 32
#define TLEN  4096
#define HCH   256
#define NPOS  (BATCH*TLEN)      // 131072
#define LLAYER 4
#define OUTCH 58
#define OPAD  64

// ---------------- scratch ----------------
__device__ float g_hA[NPOS*HCH];              // ping-pong hidden buffers
__device__ float g_hB[NPOS*HCH];
__device__ float g_wt[LLAYER*HCH*HCH];        // tf32 weights, chunk-tiled swizzled
__device__ float g_p[NPOS*OPAD];
__device__ __nv_bfloat16 g_pwh[4*OPAD*OPAD];  // proj weights bf16 hi/lo swizzled
__device__ __nv_bfloat16 g_pwl[4*OPAD*OPAD];
__device__ float g_pb[OPAD];
__device__ float g_lad[BATCH*2*TLEN];

// ---------------- helpers ----------------
__device__ __forceinline__ uint32_t smem_u32(const void* p){
  uint32_t a;
  asm("{ .reg .u64 t; cvta.to.shared.u64 t, %1; cvt.u32.u64 %0, t; }" : "=r"(a) : "l"(p));
  return a;
}
__device__ __forceinline__ void ldsm4(unsigned &r0, unsigned &r1, unsigned &r2, unsigned &r3, uint32_t a){
  asm volatile("ldmatrix.sync.aligned.m8n8.x4.shared.b16 {%0,%1,%2,%3}, [%4];"
    : "=r"(r0),"=r"(r1),"=r"(r2),"=r"(r3) : "r"(a));
}
__device__ __forceinline__ void mma_tf32(float* d, const unsigned* a, unsigned b0, unsigned b1){
  asm volatile("mma.sync.aligned.m16n8k8.row.col.f32.tf32.tf32.f32 "
    "{%0,%1,%2,%3}, {%4,%5,%6,%7}, {%8,%9}, {%0,%1,%2,%3};"
    : "+f"(d[0]),"+f"(d[1]),"+f"(d[2]),"+f"(d[3])
    : "r"(a[0]),"r"(a[1]),"r"(a[2]),"r"(a[3]),"r"(b0),"r"(b1));
}
__device__ __forceinline__ void mma_bf16(float* d, const unsigned* a, unsigned b0, unsigned b1){
  asm volatile("mma.sync.aligned.m16n8k16.row.col.f32.bf16.bf16.f32 "
    "{%0,%1,%2,%3}, {%4,%5,%6,%7}, {%8,%9}, {%0,%1,%2,%3};"
    : "+f"(d[0]),"+f"(d[1]),"+f"(d[2]),"+f"(d[3])
    : "r"(a[0]),"r"(a[1]),"r"(a[2]),"r"(a[3]),"r"(b0),"r"(b1));
}
__device__ __forceinline__ float tf32_rna(float x){
  uint32_t r;
  asm("cvt.rna.tf32.f32 %0, %1;" : "=r"(r) : "f"(x));
  return __uint_as_float(r);
}
__device__ __forceinline__ float gelu_exact(float x){
  return 0.5f*x*(1.f+erff(x*0.70710678118654752f));
}
__device__ __forceinline__ float softplusf(float x){
  return (x > 20.f) ? x : log1pf(expf(x));
}

#define MBAR_INIT(mb, c)  asm volatile("mbarrier.init.shared.b64 [%0], %1;" :: "r"(mb), "r"((uint32_t)(c)) : "memory")
#define MBAR_EXPECT_TX(mb, tx) asm volatile("mbarrier.arrive.expect_tx.shared.b64 _, [%0], %1;" :: "r"(mb), "r"((uint32_t)(tx)) : "memory")
#define MBAR_WAIT(mb, par) do {                                                   \
  uint32_t _m = (mb); uint32_t _p = (par); uint32_t _d;                           \
  asm volatile("{\n\t.reg .pred p;\n\t"                                           \
    "mbarrier.try_wait.parity.acquire.cta.shared::cta.b64 p, [%1], %2;\n\t"       \
    "selp.b32 %0, 1, 0, p;\n\t}" : "=r"(_d) : "r"(_m), "r"(_p) : "memory");       \
  if (!_d) {                                                                      \
    asm volatile("{\n\t.reg .pred P1;\n\t"                                        \
      "W_%=:\n\t"                                                                 \
      "mbarrier.try_wait.parity.acquire.cta.shared::cta.b64 P1, [%0], %1, 0x989680;\n\t" \
      "@P1 bra.uni D_%=;\n\t"                                                     \
      "bra.uni W_%=;\n\t"                                                         \
      "D_%=:\n\t}" :: "r"(_m), "r"(_p) : "memory");                               \
  }                                                                               \
} while(0)

__device__ __forceinline__ void bulk_g2s(uint32_t dst, const void* src, uint32_t bytes, uint32_t mbar){
  asm volatile("cp.async.bulk.shared::cluster.global.mbarrier::complete_tx::bytes [%0], [%1], %2, [%3];"
    :: "r"(dst), "l"(src), "r"(bytes), "r"(mbar) : "memory");
}

// ---------------- weight prep: tf32 round + chunk-tiled swizzled layout ----------------
__global__ void k_wprep(const float* __restrict__ w){
  int i = blockIdx.x*256 + threadIdx.x;
  int layer = i >> 14;
  int j = i & 16383;
  int o = j >> 6;
  int cu = j & 63;
  int chunk = cu >> 3, uu = cu & 7;
  const float* src = w + (size_t)layer*65536 + o*256 + cu*4;
  float4 v = *(const float4*)src;
  v.x = tf32_rna(v.x); v.y = tf32_rna(v.y); v.z = tf32_rna(v.z); v.w = tf32_rna(v.w);
  float* dst = g_wt + (size_t)layer*65536 + chunk*8192 + o*32 + ((uu ^ (o & 7)) << 2);
  *(float4*)dst = v;
}

// ======== fused layer kernel: dwconv+LN1+GELU (prologue, -> smem A) ========
// ========   + tf32 GEMM (A resident, B bulk-async)                  ========
// ========   + bias+LN2+GELU+residual (epilogue, hs -> hd)           ========
// CTA: 64 positions x 256 out-ch, 256 threads, 8 warps (2M x 4N).
#define OFF_A   0                 // 64KB resident A (8 chunks x 8192)
#define OFF_B   65536             // 2 stages * 32768
#define OFF_PAR 131072            // 3 * 1024
#define OFF_RED 134144            // 64 rows * 8 floats
#define OFF_MBR 136192            // 2 mbarriers
#define GSMEM   136224

__global__ void __launch_bounds__(256, 1) k_layer(int layer, int srcsel, int dil,
                       const float* __restrict__ x,   const float* __restrict__ mask,
                       const float* __restrict__ pw,  const float* __restrict__ pb,
                       const float* __restrict__ sw,  const float* __restrict__ sb,
                       const float* __restrict__ gm1, const float* __restrict__ bt1,
                       const float* __restrict__ bias,
                       const float* __restrict__ gm2, const float* __restrict__ bt2){
  extern __shared__ char smem[];
  uint32_t sbase = smem_u32(smem);
  float* s_bias = (float*)(smem + OFF_PAR);
  float* s_g    = (float*)(smem + OFF_PAR + 1024);
  float* s_bt   = (float*)(smem + OFF_PAR + 2048);
  float* s_red  = (float*)(smem + OFF_RED);

  int tid = threadIdx.x, lane = tid & 31, w = tid >> 5;
  int n0 = blockIdx.x * 64;

  const float* hs = srcsel ? g_hB : g_hA;
  float*       hd = srcsel ? g_hA : g_hB;
  const char*  gB = (const char*)(g_wt + (size_t)layer*65536);

  s_bias[tid] = bias[tid]; s_g[tid] = gm2[tid]; s_bt[tid] = bt2[tid];
  if (tid == 0){ MBAR_INIT(sbase + OFF_MBR, 1); MBAR_INIT(sbase + OFF_MBR + 16, 1); }
  __syncthreads();

  #define ISSUE_B(q) {                                                      \
    uint32_t _mb = sbase + OFF_MBR + ((q)&1)*16;                            \
    MBAR_EXPECT_TX(_mb, 32768);                                             \
    bulk_g2s(sbase + OFF_B + ((q)&1)*32768, gB + (size_t)(q)*32768, 32768, _mb); \
  }
  if (tid == 0){ ISSUE_B(0); ISSUE_B(1); }

  // ================= prologue: dwln for own 64 rows -> smem A =================
  {
    int c = lane*8;
    float s3[24], sbv[8], gmv[8], btv[8];
    #pragma unroll
    for (int q=0;q<6;q++) *(float4*)&s3[q*4] = *(const float4*)&sw[c*3 + q*4];
    *(float4*)&sbv[0] = *(const float4*)&sb[c];  *(float4*)&sbv[4] = *(const float4*)&sb[c+4];
    *(float4*)&gmv[0] = *(const float4*)&gm1[c]; *(float4*)&gmv[4] = *(const float4*)&gm1[c+4];
    *(float4*)&btv[0] = *(const float4*)&bt1[c]; *(float4*)&btv[4] = *(const float4*)&bt1[c+4];

    float pwv[16], pbv[8];
    if (layer == 0){
      #pragma unroll
      for (int q=0;q<4;q++) *(float4*)&pwv[q*4] = *(const float4*)&pw[c*2 + q*4];
      *(float4*)&pbv[0] = *(const float4*)&pb[c]; *(float4*)&pbv[4] = *(const float4*)&pb[c+4];
    }

    for (int p=0; p<8; p++){
      int row = w*8 + p;
      int n = n0 + row;
      int t = n & (TLEN-1);
      float v[8];

      if (layer == 0){
        int b4 = (n >> 12) * 4;
        float x0c = x[b4*TLEN + t], x1c = x[(b4+1)*TLEN + t];
        float m0 = mask[n];
        bool hasL = (t >= 1), hasR = (t + 1 < TLEN);
        float x0l=0.f,x1l=0.f,ml=0.f,x0r=0.f,x1r=0.f,mr_=0.f;
        if (hasL){ x0l = x[b4*TLEN + t-1]; x1l = x[(b4+1)*TLEN + t-1]; ml = mask[n-1]; }
        if (hasR){ x0r = x[b4*TLEN + t+1]; x1r = x[(b4+1)*TLEN + t+1]; mr_ = mask[n+1]; }
        float hc[8];
        #pragma unroll
        for (int j=0;j<8;j++){
          float wa = pwv[j*2], wb = pwv[j*2+1], pbc = pbv[j];
          float h0 = fmaf(wa, x0c, fmaf(wb, x1c, pbc));
          hc[j] = h0;
          float acc = sbv[j] + s3[j*3+1]*h0*m0;
          if (hasL){ float hl = fmaf(wa, x0l, fmaf(wb, x1l, pbc)); acc += s3[j*3+0]*hl*ml; }
          if (hasR){ float hr = fmaf(wa, x0r, fmaf(wb, x1r, pbc)); acc += s3[j*3+2]*hr*mr_; }
          v[j] = acc;
        }
        // seed h_src (g_hA) for epilogue residual read
        *(float4*)&g_hA[(size_t)n*HCH + c]     = *(float4*)&hc[0];
        *(float4*)&g_hA[(size_t)n*HCH + c + 4] = *(float4*)&hc[4];
      } else {
        float m0 = mask[n];
        float hc[8];
        *(float4*)&hc[0] = *(const float4*)&hs[(size_t)n*HCH + c];
        *(float4*)&hc[4] = *(const float4*)&hs[(size_t)n*HCH + c + 4];
        #pragma unroll
        for (int j=0;j<8;j++) v[j] = sbv[j] + s3[j*3+1]*hc[j]*m0;
        if (t >= dil){
          float mm = mask[n-dil];
          float hl[8];
          *(float4*)&hl[0] = *(const float4*)&hs[(size_t)(n-dil)*HCH + c];
          *(float4*)&hl[4] = *(const float4*)&hs[(size_t)(n-dil)*HCH + c + 4];
          #pragma unroll
          for (int j=0;j<8;j++) v[j] += s3[j*3+0]*hl[j]*mm;
        }
        if (t + dil < TLEN){
          float mm = mask[n+dil];
          float hr[8];
          *(float4*)&hr[0] = *(const float4*)&hs[(size_t)(n+dil)*HCH + c];
          *(float4*)&hr[4] = *(const float4*)&hs[(size_t)(n+dil)*HCH + c + 4];
          #pragma unroll
          for (int j=0;j<8;j++) v[j] += s3[j*3+2]*hr[j]*mm;
        }
      }

      float ls = 0.f;
      #pragma unroll
      for (int j=0;j<8;j++) ls += v[j];
      #pragma unroll
      for (int o=16;o;o>>=1) ls += __shfl_xor_sync(0xffffffffu, ls, o);
      float mean = ls * (1.f/HCH);
      float sq = 0.f;
      #pragma unroll
      for (int j=0;j<8;j++){ v[j] -= mean; sq += v[j]*v[j]; }
      #pragma unroll
      for (int o=16;o;o>>=1) sq += __shfl_xor_sync(0xffffffffu, sq, o);
      float rstd = rsqrtf(sq * (1.f/HCH) + 1e-5f);

      float o_[8];
      #pragma unroll
      for (int j=0;j<8;j++){
        float yn = v[j]*rstd*gmv[j] + btv[j];
        o_[j] = tf32_rna(gelu_exact(yn));
      }
      // store swizzled into smem A: [chunk][row][32f], unit u at u^(row&7)
      int cu0 = c >> 2;
      int chunk = cu0 >> 3, uu = cu0 & 7;
      int r7 = row & 7;
      char* abase = smem + OFF_A + chunk*8192 + row*128;
      *(float4*)(abase + ((uu ^ r7) << 4))     = *(float4*)&o_[0];
      *(float4*)(abase + (((uu+1) ^ r7) << 4)) = *(float4*)&o_[4];
    }
  }
  __syncthreads();

  // ================= mainloop =================
  int warpM = w >> 2, warpN = w & 3;
  int g = lane >> 2, tig = lane & 3;
  int mat = lane >> 3, mr = lane & 7;

  float acc[2][8][4];
  #pragma unroll
  for (int mf=0;mf<2;mf++)
    #pragma unroll
    for (int nf=0;nf<8;nf++)
      #pragma unroll
      for (int k=0;k<4;k++) acc[mf][nf][k]=0.f;

  int arow_l = (mat & 1)*8 + mr;   int amh = mat >> 1;
  int brow_l = (mat >> 1)*8 + mr;  int bmh = mat & 1;
  uint32_t aBase0 = sbase + OFF_A + (uint32_t)((warpM*32 + arow_l)*128);
  uint32_t bBase0 = sbase + OFF_B + (uint32_t)((warpN*64 + brow_l)*128);

  for (int q = 0; q < 8; q++){
    MBAR_WAIT(sbase + OFF_MBR + (q&1)*16, (q>>1)&1);

    uint32_t aBase = aBase0 + q*8192;
    uint32_t bBase = bBase0 + (q&1)*32768;

    #pragma unroll
    for (int ks=0; ks<4; ks++){
      uint32_t swa = (uint32_t)(((2*ks + amh) ^ mr) << 4);
      uint32_t swb = (uint32_t)(((2*ks + bmh) ^ mr) << 4);
      unsigned afr[2][4];
      ldsm4(afr[0][0], afr[0][1], afr[0][2], afr[0][3], aBase + swa);
      ldsm4(afr[1][0], afr[1][1], afr[1][2], afr[1][3], aBase + 2048 + swa);
      unsigned bfr[8][2];
      #pragma unroll
      for (int np=0; np<4; np++){
        unsigned t0,t1,t2,t3;
        ldsm4(t0,t1,t2,t3, bBase + np*2048 + swb);
        bfr[2*np][0]=t0; bfr[2*np][1]=t1; bfr[2*np+1][0]=t2; bfr[2*np+1][1]=t3;
      }
      #pragma unroll
      for (int nf=0; nf<8; nf++){
        mma_tf32(acc[0][nf], afr[0], bfr[nf][0], bfr[nf][1]);
        mma_tf32(acc[1][nf], afr[1], bfr[nf][0], bfr[nf][1]);
      }
    }
    __syncthreads();
    if (tid == 0 && q + 2 < 8) ISSUE_B(q+2);
  }

  // ================= epilogue: bias, LN2, GELU, residual hs->hd =================
  float s[4]  = {0.f,0.f,0.f,0.f};
  float sq[4] = {0.f,0.f,0.f,0.f};
  #pragma unroll
  for (int mf=0; mf<2; mf++)
    #pragma unroll
    for (int nf=0; nf<8; nf++){
      int ch0 = warpN*64 + nf*8 + tig*2;
      float b0 = s_bias[ch0], b1 = s_bias[ch0+1];
      acc[mf][nf][0]+=b0; acc[mf][nf][1]+=b1;
      acc[mf][nf][2]+=b0; acc[mf][nf][3]+=b1;
      s [mf*2+0] += acc[mf][nf][0]+acc[mf][nf][1];
      sq[mf*2+0] += acc[mf][nf][0]*acc[mf][nf][0] + acc[mf][nf][1]*acc[mf][nf][1];
      s [mf*2+1] += acc[mf][nf][2]+acc[mf][nf][3];
      sq[mf*2+1] += acc[mf][nf][2]*acc[mf][nf][2] + acc[mf][nf][3]*acc[mf][nf][3];
    }
  #pragma unroll
  for (int sl=0; sl<4; sl++){
    s [sl] += __shfl_xor_sync(0xffffffffu, s [sl], 1);
    s [sl] += __shfl_xor_sync(0xffffffffu, s [sl], 2);
    sq[sl] += __shfl_xor_sync(0xffffffffu, sq[sl], 1);
    sq[sl] += __shfl_xor_sync(0xffffffffu, sq[sl], 2);
  }
  __syncthreads();
  if (tig == 0){
    #pragma unroll
    for (int sl=0; sl<4; sl++){
      int mf = sl >> 1, h = sl & 1;
      int row = warpM*32 + mf*16 + h*8 + g;
      s_red[row*8 + warpN*2 + 0] = s[sl];
      s_red[row*8 + warpN*2 + 1] = sq[sl];
    }
  }
  __syncthreads();

  float mean_[4], rstd_[4];
  #pragma unroll
  for (int sl=0; sl<4; sl++){
    int mf = sl >> 1, h = sl & 1;
    int row = warpM*32 + mf*16 + h*8 + g;
    float su = s_red[row*8+0]+s_red[row*8+2]+s_red[row*8+4]+s_red[row*8+6];
    float qq = s_red[row*8+1]+s_red[row*8+3]+s_red[row*8+5]+s_red[row*8+7];
    float mn = su * (1.f/HCH);
    float var = qq * (1.f/HCH) - mn*mn;
    mean_[sl] = mn;
    rstd_[sl] = rsqrtf(var + 1e-5f);
  }

  #pragma unroll
  for (int mf=0; mf<2; mf++)
    #pragma unroll
    for (int nf=0; nf<8; nf++){
      int ch0 = warpN*64 + nf*8 + tig*2;
      float g0 = s_g[ch0], g1 = s_g[ch0+1];
      float t0 = s_bt[ch0], t1 = s_bt[ch0+1];
      #pragma unroll
      for (int h=0; h<2; h++){
        int sl = mf*2 + h;
        int row = n0 + warpM*32 + mf*16 + h*8 + g;
        float v0 = (acc[mf][nf][h*2+0] - mean_[sl])*rstd_[sl]*g0 + t0;
        float v1 = (acc[mf][nf][h*2+1] - mean_[sl])*rstd_[sl]*g1 + t1;
        float2 hv = *(const float2*)&hs[(size_t)row*HCH + ch0];
        hv.x += gelu_exact(v0);
        hv.y += gelu_exact(v1);
        *(float2*)&hd[(size_t)row*HCH + ch0] = hv;
      }
    }
}

// ---------------- proj weight prep: bf16 hi/lo, chunked swizzled ----------------
__global__ void k_padw(const float* __restrict__ pjw, const float* __restrict__ pjb){
  int o = blockIdx.x, k = threadIdx.x;
  float w = (o < OUTCH) ? pjw[o*HCH + k] : 0.f;
  __nv_bfloat16 h = __float2bfloat16(w);
  __nv_bfloat16 l = __float2bfloat16(w - __bfloat162float(h));
  int chunk = k >> 6;
  int kk = k & 63;
  int uu = kk >> 3, pos = kk & 7;
  int off = chunk*4096 + o*64 + ((uu ^ (o & 7)) << 3) + pos;
  g_pwh[off] = h;
  g_pwl[off] = l;
  if (k == 0) g_pb[o] = (o < OUTCH) ? pjb[o] : 0.f;
}

// ---------------- projection: bf16 hi/lo mma, g_p = (W(h*m)+b)*m ----------------
// reads g_hA (final hidden after layer 3)
__global__ void __launch_bounds__(256) k_projmma(const float* __restrict__ mask){
  __shared__ __nv_bfloat16 sAh[64*64], sAl[64*64], sBh[64*64], sBl[64*64];
  __shared__ float s_pb[64];
  int tid = threadIdx.x, lane = tid & 31, wid = tid >> 5;
  int warpM = wid & 3, warpN = wid >> 2;
  int g = lane >> 2, tig = lane & 3;
  int mat = lane >> 3, mr = lane & 7;
  int n0 = blockIdx.x * 64;
  if (tid < 64) s_pb[tid] = g_pb[tid];

  uint32_t sah = smem_u32(sAh), sal = smem_u32(sAl);
  uint32_t sbh = smem_u32(sBh), sbl = smem_u32(sBl);

  float acc[4][4];
  #pragma unroll
  for (int nf=0;nf<4;nf++)
    #pragma unroll
    for (int k=0;k<4;k++) acc[nf][k]=0.f;

  int arow_l = (mat & 1)*8 + mr;   int amh = mat >> 1;
  int brow_l = (mat >> 1)*8 + mr;  int bmh = mat & 1;
  uint32_t aOffW = (uint32_t)((warpM*16 + arow_l)*128);
  uint32_t bOffW = (uint32_t)((warpN*32 + brow_l)*128);

  int row = tid >> 2;
  int kq  = (tid & 3) * 16;
  float m_row = mask[n0 + row];
  int r7 = row & 7;
  int u0 = (tid & 3) * 2;

  for (int chunk=0; chunk<4; chunk++){
    __syncthreads();
    {
      float hv[16];
      const float* src = &g_hA[(size_t)(n0+row)*HCH + chunk*64 + kq];
      *(float4*)&hv[0]  = *(const float4*)&src[0];
      *(float4*)&hv[4]  = *(const float4*)&src[4];
      *(float4*)&hv[8]  = *(const float4*)&src[8];
      *(float4*)&hv[12] = *(const float4*)&src[12];
      __nv_bfloat16 hi[16], lo[16];
      #pragma unroll
      for (int j=0;j<16;j++){
        float v = hv[j]*m_row;
        __nv_bfloat16 h = __float2bfloat16(v);
        hi[j] = h;
        lo[j] = __float2bfloat16(v - __bfloat162float(h));
      }
      uint32_t o0 = (uint32_t)(row*128 + ((u0 ^ r7) << 4));
      uint32_t o1 = (uint32_t)(row*128 + (((u0+1) ^ r7) << 4));
      *(uint4*)((char*)sAh + o0) = *(uint4*)&hi[0];
      *(uint4*)((char*)sAh + o1) = *(uint4*)&hi[8];
      *(uint4*)((char*)sAl + o0) = *(uint4*)&lo[0];
      *(uint4*)((char*)sAl + o1) = *(uint4*)&lo[8];
    }
    {
      const uint4* srcH = (const uint4*)&g_pwh[chunk*4096];
      const uint4* srcL = (const uint4*)&g_pwl[chunk*4096];
      ((uint4*)sBh)[tid]       = srcH[tid];
      ((uint4*)sBh)[tid + 256] = srcH[tid + 256];
      ((uint4*)sBl)[tid]       = srcL[tid];
      ((uint4*)sBl)[tid + 256] = srcL[tid + 256];
    }
    __syncthreads();

    #pragma unroll
    for (int kst=0; kst<4; kst++){
      uint32_t ua = (uint32_t)(((2*kst + amh) ^ mr) << 4);
      uint32_t ub = (uint32_t)(((2*kst + bmh) ^ mr) << 4);
      unsigned ah[4], al[4];
      ldsm4(ah[0],ah[1],ah[2],ah[3], sah + aOffW + ua);
      ldsm4(al[0],al[1],al[2],al[3], sal + aOffW + ua);
      unsigned bh[4][2], bl[4][2];
      #pragma unroll
      for (int np=0; np<2; np++){
        unsigned t0,t1,t2,t3;
        ldsm4(t0,t1,t2,t3, sbh + bOffW + np*2048 + ub);
        bh[2*np][0]=t0; bh[2*np][1]=t1; bh[2*np+1][0]=t2; bh[2*np+1][1]=t3;
        ldsm4(t0,t1,t2,t3, sbl + bOffW + np*2048 + ub);
        bl[2*np][0]=t0; bl[2*np][1]=t1; bl[2*np+1][0]=t2; bl[2*np+1][1]=t3;
      }
      #pragma unroll
      for (int nf=0; nf<4; nf++){
        mma_bf16(acc[nf], ah, bh[nf][0], bh[nf][1]);
        mma_bf16(acc[nf], ah, bl[nf][0], bl[nf][1]);
        mma_bf16(acc[nf], al, bh[nf][0], bh[nf][1]);
      }
    }
  }

  #pragma unroll
  for (int nf=0; nf<4; nf++){
    int ch0 = warpN*32 + nf*8 + tig*2;
    float b0 = s_pb[ch0], b1 = s_pb[ch0+1];
    #pragma unroll
    for (int h=0; h<2; h++){
      int r = n0 + warpM*16 + h*8 + g;
      float m = mask[r];
      float2 v;
      v.x = (acc[nf][h*2+0] + b0) * m;
      v.y = (acc[nf][h*2+1] + b1) * m;
      *(float2*)&g_p[(size_t)r*OPAD + ch0] = v;
    }
  }
}

// ---------------- rational-quadratic spline ----------------
__global__ void k_spline(const float* __restrict__ x, const float* __restrict__ mask,
                         float* __restrict__ out){
  int i = blockIdx.x*256 + threadIdx.x;
  int t = i & (TLEN-1);
  int bc = i >> 12;
  int c = bc & 1, b = bc >> 1;
  float m = mask[b*TLEN + t];
  const float* p = &g_p[(size_t)(b*TLEN + t)*OPAD + c*29];
  float x1 = x[(b*4 + 2 + c)*TLEN + t];

  out[(b*4 + c)*TLEN + t] = x[(b*4 + c)*TLEN + t] * m;

  const float scale = 0.0625f;
  float ew[10], eh[10];
  float mw = -1e30f, mh = -1e30f;
  #pragma unroll
  for (int j=0;j<10;j++){ mw = fmaxf(mw, p[j]*scale); mh = fmaxf(mh, p[10+j]*scale); }
  float sw = 0.f, sh = 0.f;
  #pragma unroll
  for (int j=0;j<10;j++){
    ew[j] = expf(p[j]*scale - mw);    sw += ew[j];
    eh[j] = expf(p[10+j]*scale - mh); sh += eh[j];
  }
  float invsw = 1.f/sw, invsh = 1.f/sh;
  float xc = fminf(fmaxf(x1, -5.f), 5.f);

  float cumw = 0.f, cumh = 0.f;
  float cwj = -5.f, chj = -5.f;
  int idx = 9;
  float in_cw = 0.f, in_w = 1.f, in_ch = 0.f, in_h = 1.f;
  bool found = false;
  #pragma unroll
  for (int j=0;j<10;j++){
    cumw += 0.001f + 0.99f*ew[j]*invsw;
    cumh += 0.001f + 0.99f*eh[j]*invsh;
    float nw = (j==9) ? 5.f : fmaf(10.f, cumw, -5.f);
    float nh = (j==9) ? 5.f : fmaf(10.f, cumh, -5.f);
    if (!found && (xc < nw || j==9)){
      found = true; idx = j;
      in_cw = cwj; in_w = nw - cwj;
      in_ch = chj; in_h = nh - chj;
    }
    cwj = nw; chj = nh;
  }
  float dk  = (idx==0) ? 1.f : 0.001f + softplusf(p[20 + idx - 1]);
  float dk1 = (idx==9) ? 1.f : 0.001f + softplusf(p[20 + idx]);
  float delta = in_h / in_w;
  float th  = (xc - in_cw) / in_w;
  float th2 = th*th;
  float t1m = th*(1.f - th);
  float num = in_h * (delta*th2 + dk*t1m);
  float den = delta + (dk + dk1 - 2.f*delta)*t1m;
  float y = in_ch + num/den;
  float omt = 1.f - th;
  float dnum = delta*delta*(dk1*th2 + 2.f*delta*t1m + dk*omt*omt);
  float lad = logf(dnum) - 2.f*logf(den);

  bool inside = (x1 >= -5.f) && (x1 <= 5.f);
  y   = inside ? y   : x1;
  lad = inside ? lad : 0.f;

  out[(b*4 + 2 + c)*TLEN + t] = y * m;
  g_lad[i] = lad * m;
}

__global__ void k_reduce(float* __restrict__ out){
  int b = blockIdx.x;
  float s = 0.f;
  for (int j = threadIdx.x; j < 2*TLEN; j += 256) s += g_lad[b*2*TLEN + j];
  __shared__ float sm[8];
  #pragma unroll
  for (int o=16;o;o>>=1) s += __shfl_xor_sync(0xffffffffu, s, o);
  if ((threadIdx.x&31)==0) sm[threadIdx.x>>5]=s;
  __syncthreads();
  if (threadIdx.x == 0){
    float r = sm[0]+sm[1]+sm[2]+sm[3]+sm[4]+sm[5]+sm[6]+sm[7];
    out[BATCH*4*TLEN + b] = r;
  }
}

extern "C" void kernel_launch(void* const* d_in, const int* in_sizes, int n_in,
                              void* d_out, int out_size){
  const float* x     = (const float*)d_in[0];
  const float* xm    = (const float*)d_in[1];
  const float* pre_w = (const float*)d_in[2];
  const float* pre_b = (const float*)d_in[3];
  const float* sep_w = (const float*)d_in[4];
  const float* sep_b = (const float*)d_in[5];
  const float* c1w   = (const float*)d_in[6];
  const float* c1b   = (const float*)d_in[7];
  const float* n1g   = (const float*)d_in[8];
  const float* n1b   = (const float*)d_in[9];
  const float* n2g   = (const float*)d_in[10];
  const float* n2b   = (const float*)d_in[11];
  const float* pjw   = (const float*)d_in[12];
  const float* pjb   = (const float*)d_in[13];
  float* out = (float*)d_out;

  static int smem_set = 0;
  if (!smem_set){
    cudaFuncSetAttribute(k_layer, cudaFuncAttributeMaxDynamicSharedMemorySize, GSMEM);
    smem_set = 1;
  }

  k_wprep<<<(LLAYER*HCH*HCH/4)/256, 256>>>(c1w);
  k_padw<<<OPAD, HCH>>>(pjw, pjb);

  int dil = 1;
  for (int i=0;i<LLAYER;i++){
    int srcsel = i & 1;   // L0: src A, dst B; L1: src B, dst A; ... L3 dst = A
    k_layer<<<NPOS/64, 256, GSMEM>>>(i, srcsel, dil, x, xm,
        pre_w, pre_b,
        sep_w + i*HCH*3, sep_b + i*HCH,
        n1g + i*HCH, n1b + i*HCH,
        c1b + i*HCH,
        n2g + i*HCH, n2b + i*HCH);
    dil *= 3;
  }

  k_projmma<<<NPOS/64, 256>>>(xm);
  k_spline<<<(BATCH*2*TLEN)/256, 256>>>(x, xm, out);
  k_reduce<<<BATCH, 256>>>(out);
}

// round 17
// speedup vs baseline: 1.4106x; 1.4091x over previous
#include <cuda_runtime.h>
#include <cuda_bf16.h>
#include <math.h>
#include <stdint.h>

#define BATCH 32
#define TLEN  4096
#define HCH   256
#define NPOS  (BATCH*TLEN)      // 131072
#define LLAYER 4
#define OUTCH 58
#define OPAD  64

// ---------------- scratch ----------------
__device__ float g_hA[NPOS*HCH];              // ping-pong hidden buffers
__device__ float g_hB[NPOS*HCH];
__device__ float g_wt[LLAYER*HCH*HCH];        // tf32 weights, chunk-tiled swizzled
__device__ float g_p[NPOS*OPAD];
__device__ __nv_bfloat16 g_pwh[4*OPAD*OPAD];  // proj weights bf16 hi/lo swizzled
__device__ __nv_bfloat16 g_pwl[4*OPAD*OPAD];
__device__ float g_pb[OPAD];
__device__ float g_lad[BATCH*2*TLEN];

// ---------------- helpers ----------------
__device__ __forceinline__ uint32_t smem_u32(const void* p){
  uint32_t a;
  asm("{ .reg .u64 t; cvta.to.shared.u64 t, %1; cvt.u32.u64 %0, t; }" : "=r"(a) : "l"(p));
  return a;
}
__device__ __forceinline__ void ldsm4(unsigned &r0, unsigned &r1, unsigned &r2, unsigned &r3, uint32_t a){
  asm volatile("ldmatrix.sync.aligned.m8n8.x4.shared.b16 {%0,%1,%2,%3}, [%4];"
    : "=r"(r0),"=r"(r1),"=r"(r2),"=r"(r3) : "r"(a));
}
__device__ __forceinline__ void mma_tf32(float* d, const unsigned* a, unsigned b0, unsigned b1){
  asm volatile("mma.sync.aligned.m16n8k8.row.col.f32.tf32.tf32.f32 "
    "{%0,%1,%2,%3}, {%4,%5,%6,%7}, {%8,%9}, {%0,%1,%2,%3};"
    : "+f"(d[0]),"+f"(d[1]),"+f"(d[2]),"+f"(d[3])
    : "r"(a[0]),"r"(a[1]),"r"(a[2]),"r"(a[3]),"r"(b0),"r"(b1));
}
__device__ __forceinline__ void mma_bf16(float* d, const unsigned* a, unsigned b0, unsigned b1){
  asm volatile("mma.sync.aligned.m16n8k16.row.col.f32.bf16.bf16.f32 "
    "{%0,%1,%2,%3}, {%4,%5,%6,%7}, {%8,%9}, {%0,%1,%2,%3};"
    : "+f"(d[0]),"+f"(d[1]),"+f"(d[2]),"+f"(d[3])
    : "r"(a[0]),"r"(a[1]),"r"(a[2]),"r"(a[3]),"r"(b0),"r"(b1));
}
__device__ __forceinline__ float tf32_rna(float x){
  uint32_t r;
  asm("cvt.rna.tf32.f32 %0, %1;" : "=r"(r) : "f"(x));
  return __uint_as_float(r);
}
__device__ __forceinline__ float gelu_exact(float x){
  return 0.5f*x*(1.f+erff(x*0.70710678118654752f));
}
__device__ __forceinline__ float softplusf(float x){
  return (x > 20.f) ? x : log1pf(expf(x));
}

#define MBAR_INIT(mb, c)  asm volatile("mbarrier.init.shared.b64 [%0], %1;" :: "r"(mb), "r"((uint32_t)(c)) : "memory")
#define MBAR_EXPECT_TX(mb, tx) asm volatile("mbarrier.arrive.expect_tx.shared.b64 _, [%0], %1;" :: "r"(mb), "r"((uint32_t)(tx)) : "memory")
#define MBAR_WAIT(mb, par) do {                                                   \
  uint32_t _m = (mb); uint32_t _p = (par); uint32_t _d;                           \
  asm volatile("{\n\t.reg .pred p;\n\t"                                           \
    "mbarrier.try_wait.parity.acquire.cta.shared::cta.b64 p, [%1], %2;\n\t"       \
    "selp.b32 %0, 1, 0, p;\n\t}" : "=r"(_d) : "r"(_m), "r"(_p) : "memory");       \
  if (!_d) {                                                                      \
    asm volatile("{\n\t.reg .pred P1;\n\t"                                        \
      "W_%=:\n\t"                                                                 \
      "mbarrier.try_wait.parity.acquire.cta.shared::cta.b64 P1, [%0], %1, 0x989680;\n\t" \
      "@P1 bra.uni D_%=;\n\t"                                                     \
      "bra.uni W_%=;\n\t"                                                         \
      "D_%=:\n\t}" :: "r"(_m), "r"(_p) : "memory");                               \
  }                                                                               \
} while(0)

__device__ __forceinline__ void bulk_g2s(uint32_t dst, const void* src, uint32_t bytes, uint32_t mbar){
  asm volatile("cp.async.bulk.shared::cluster.global.mbarrier::complete_tx::bytes [%0], [%1], %2, [%3];"
    :: "r"(dst), "l"(src), "r"(bytes), "r"(mbar) : "memory");
}

// ---------------- weight prep: tf32 round + chunk-tiled swizzled layout ----------------
__global__ void k_wprep(const float* __restrict__ w){
  int i = blockIdx.x*256 + threadIdx.x;
  int layer = i >> 14;
  int j = i & 16383;
  int o = j >> 6;
  int cu = j & 63;
  int chunk = cu >> 3, uu = cu & 7;
  const float* src = w + (size_t)layer*65536 + o*256 + cu*4;
  float4 v = *(const float4*)src;
  v.x = tf32_rna(v.x); v.y = tf32_rna(v.y); v.z = tf32_rna(v.z); v.w = tf32_rna(v.w);
  float* dst = g_wt + (size_t)layer*65536 + chunk*8192 + o*32 + ((uu ^ (o & 7)) << 2);
  *(float4*)dst = v;
}

// ======== fused layer kernel v2: 2 CTAs/SM ========
// prologue: dwconv+LN1+GELU -> resident smem A (64KB, 8 chunks)
// mainloop: tf32 GEMM, B single-buffered bulk-async (32KB)
// epilogue: bias+LN2+GELU+residual hs -> hd
#define OFF_A   0                 // 8 chunks x 8192 = 65536
#define OFF_B   65536             // 1 stage * 32768
#define OFF_PAR 98304             // 3 * 1024
#define OFF_RED 101376            // 64 rows * 8 floats
#define OFF_MBR 103424            // 1 mbarrier
#define GSMEM   103456

__global__ void __launch_bounds__(256, 2) k_layer(int layer, int srcsel, int dil,
                       const float* __restrict__ x,   const float* __restrict__ mask,
                       const float* __restrict__ pw,  const float* __restrict__ pb,
                       const float* __restrict__ sw,  const float* __restrict__ sb,
                       const float* __restrict__ gm1, const float* __restrict__ bt1,
                       const float* __restrict__ bias,
                       const float* __restrict__ gm2, const float* __restrict__ bt2){
  extern __shared__ char smem[];
  uint32_t sbase = smem_u32(smem);
  float* s_bias = (float*)(smem + OFF_PAR);
  float* s_g    = (float*)(smem + OFF_PAR + 1024);
  float* s_bt   = (float*)(smem + OFF_PAR + 2048);
  float* s_red  = (float*)(smem + OFF_RED);

  int tid = threadIdx.x, lane = tid & 31, w = tid >> 5;
  int n0 = blockIdx.x * 64;

  const float* hs = srcsel ? g_hB : g_hA;
  float*       hd = srcsel ? g_hA : g_hB;
  const char*  gB = (const char*)(g_wt + (size_t)layer*65536);

  s_bias[tid] = bias[tid]; s_g[tid] = gm2[tid]; s_bt[tid] = bt2[tid];
  if (tid == 0) MBAR_INIT(sbase + OFF_MBR, 1);
  __syncthreads();

  #define ISSUE_B(q) {                                                      \
    uint32_t _mb = sbase + OFF_MBR;                                         \
    MBAR_EXPECT_TX(_mb, 32768);                                             \
    bulk_g2s(sbase + OFF_B, gB + (size_t)(q)*32768, 32768, _mb);            \
  }
  if (tid == 0) ISSUE_B(0);   // overlaps prologue

  // ================= prologue: dwln for own 64 rows -> smem A =================
  {
    int c = lane*8;
    float s3[24], sbv[8], gmv[8], btv[8];
    #pragma unroll
    for (int q=0;q<6;q++) *(float4*)&s3[q*4] = *(const float4*)&sw[c*3 + q*4];
    *(float4*)&sbv[0] = *(const float4*)&sb[c];  *(float4*)&sbv[4] = *(const float4*)&sb[c+4];
    *(float4*)&gmv[0] = *(const float4*)&gm1[c]; *(float4*)&gmv[4] = *(const float4*)&gm1[c+4];
    *(float4*)&btv[0] = *(const float4*)&bt1[c]; *(float4*)&btv[4] = *(const float4*)&bt1[c+4];

    float pwv[16], pbv[8];
    if (layer == 0){
      #pragma unroll
      for (int q=0;q<4;q++) *(float4*)&pwv[q*4] = *(const float4*)&pw[c*2 + q*4];
      *(float4*)&pbv[0] = *(const float4*)&pb[c]; *(float4*)&pbv[4] = *(const float4*)&pb[c+4];
    }

    for (int p=0; p<8; p++){
      int row = w*8 + p;
      int n = n0 + row;
      int t = n & (TLEN-1);
      float v[8];

      if (layer == 0){
        int b4 = (n >> 12) * 4;
        float x0c = x[b4*TLEN + t], x1c = x[(b4+1)*TLEN + t];
        float m0 = mask[n];
        bool hasL = (t >= 1), hasR = (t + 1 < TLEN);
        float x0l=0.f,x1l=0.f,ml=0.f,x0r=0.f,x1r=0.f,mr_=0.f;
        if (hasL){ x0l = x[b4*TLEN + t-1]; x1l = x[(b4+1)*TLEN + t-1]; ml = mask[n-1]; }
        if (hasR){ x0r = x[b4*TLEN + t+1]; x1r = x[(b4+1)*TLEN + t+1]; mr_ = mask[n+1]; }
        float hc[8];
        #pragma unroll
        for (int j=0;j<8;j++){
          float wa = pwv[j*2], wb = pwv[j*2+1], pbc = pbv[j];
          float h0 = fmaf(wa, x0c, fmaf(wb, x1c, pbc));
          hc[j] = h0;
          float acc = sbv[j] + s3[j*3+1]*h0*m0;
          if (hasL){ float hl = fmaf(wa, x0l, fmaf(wb, x1l, pbc)); acc += s3[j*3+0]*hl*ml; }
          if (hasR){ float hr = fmaf(wa, x0r, fmaf(wb, x1r, pbc)); acc += s3[j*3+2]*hr*mr_; }
          v[j] = acc;
        }
        *(float4*)&g_hA[(size_t)n*HCH + c]     = *(float4*)&hc[0];
        *(float4*)&g_hA[(size_t)n*HCH + c + 4] = *(float4*)&hc[4];
      } else {
        float m0 = mask[n];
        float hc[8];
        *(float4*)&hc[0] = *(const float4*)&hs[(size_t)n*HCH + c];
        *(float4*)&hc[4] = *(const float4*)&hs[(size_t)n*HCH + c + 4];
        #pragma unroll
        for (int j=0;j<8;j++) v[j] = sbv[j] + s3[j*3+1]*hc[j]*m0;
        if (t >= dil){
          float mm = mask[n-dil];
          float hl[8];
          *(float4*)&hl[0] = *(const float4*)&hs[(size_t)(n-dil)*HCH + c];
          *(float4*)&hl[4] = *(const float4*)&hs[(size_t)(n-dil)*HCH + c + 4];
          #pragma unroll
          for (int j=0;j<8;j++) v[j] += s3[j*3+0]*hl[j]*mm;
        }
        if (t + dil < TLEN){
          float mm = mask[n+dil];
          float hr[8];
          *(float4*)&hr[0] = *(const float4*)&hs[(size_t)(n+dil)*HCH + c];
          *(float4*)&hr[4] = *(const float4*)&hs[(size_t)(n+dil)*HCH + c + 4];
          #pragma unroll
          for (int j=0;j<8;j++) v[j] += s3[j*3+2]*hr[j]*mm;
        }
      }

      float ls = 0.f;
      #pragma unroll
      for (int j=0;j<8;j++) ls += v[j];
      #pragma unroll
      for (int o=16;o;o>>=1) ls += __shfl_xor_sync(0xffffffffu, ls, o);
      float mean = ls * (1.f/HCH);
      float sq = 0.f;
      #pragma unroll
      for (int j=0;j<8;j++){ v[j] -= mean; sq += v[j]*v[j]; }
      #pragma unroll
      for (int o=16;o;o>>=1) sq += __shfl_xor_sync(0xffffffffu, sq, o);
      float rstd = rsqrtf(sq * (1.f/HCH) + 1e-5f);

      float o_[8];
      #pragma unroll
      for (int j=0;j<8;j++){
        float yn = v[j]*rstd*gmv[j] + btv[j];
        o_[j] = tf32_rna(gelu_exact(yn));
      }
      int cu0 = c >> 2;
      int chunk = cu0 >> 3, uu = cu0 & 7;
      int r7 = row & 7;
      char* abase = smem + OFF_A + chunk*8192 + row*128;
      *(float4*)(abase + ((uu ^ r7) << 4))     = *(float4*)&o_[0];
      *(float4*)(abase + (((uu+1) ^ r7) << 4)) = *(float4*)&o_[4];
    }
  }
  __syncthreads();

  // ================= mainloop (B single-buffered) =================
  int warpM = w >> 2, warpN = w & 3;
  int g = lane >> 2, tig = lane & 3;
  int mat = lane >> 3, mr = lane & 7;

  float acc[2][8][4];
  #pragma unroll
  for (int mf=0;mf<2;mf++)
    #pragma unroll
    for (int nf=0;nf<8;nf++)
      #pragma unroll
      for (int k=0;k<4;k++) acc[mf][nf][k]=0.f;

  int arow_l = (mat & 1)*8 + mr;   int amh = mat >> 1;
  int brow_l = (mat >> 1)*8 + mr;  int bmh = mat & 1;
  uint32_t aBase0 = sbase + OFF_A + (uint32_t)((warpM*32 + arow_l)*128);
  uint32_t bBase  = sbase + OFF_B + (uint32_t)((warpN*64 + brow_l)*128);

  for (int q = 0; q < 8; q++){
    MBAR_WAIT(sbase + OFF_MBR, q&1);

    uint32_t aBase = aBase0 + q*8192;

    #pragma unroll
    for (int ks=0; ks<4; ks++){
      uint32_t swa = (uint32_t)(((2*ks + amh) ^ mr) << 4);
      uint32_t swb = (uint32_t)(((2*ks + bmh) ^ mr) << 4);
      unsigned afr[2][4];
      ldsm4(afr[0][0], afr[0][1], afr[0][2], afr[0][3], aBase + swa);
      ldsm4(afr[1][0], afr[1][1], afr[1][2], afr[1][3], aBase + 2048 + swa);
      unsigned bfr[8][2];
      #pragma unroll
      for (int np=0; np<4; np++){
        unsigned t0,t1,t2,t3;
        ldsm4(t0,t1,t2,t3, bBase + np*2048 + swb);
        bfr[2*np][0]=t0; bfr[2*np][1]=t1; bfr[2*np+1][0]=t2; bfr[2*np+1][1]=t3;
      }
      #pragma unroll
      for (int nf=0; nf<8; nf++){
        mma_tf32(acc[0][nf], afr[0], bfr[nf][0], bfr[nf][1]);
        mma_tf32(acc[1][nf], afr[1], bfr[nf][0], bfr[nf][1]);
      }
    }
    __syncthreads();                 // all warps done with B buffer
    if (tid == 0 && q + 1 < 8) ISSUE_B(q+1);
  }

  // ================= epilogue: bias, LN2, GELU, residual hs->hd =================
  float s[4]  = {0.f,0.f,0.f,0.f};
  float sq[4] = {0.f,0.f,0.f,0.f};
  #pragma unroll
  for (int mf=0; mf<2; mf++)
    #pragma unroll
    for (int nf=0; nf<8; nf++){
      int ch0 = warpN*64 + nf*8 + tig*2;
      float b0 = s_bias[ch0], b1 = s_bias[ch0+1];
      acc[mf][nf][0]+=b0; acc[mf][nf][1]+=b1;
      acc[mf][nf][2]+=b0; acc[mf][nf][3]+=b1;
      s [mf*2+0] += acc[mf][nf][0]+acc[mf][nf][1];
      sq[mf*2+0] += acc[mf][nf][0]*acc[mf][nf][0] + acc[mf][nf][1]*acc[mf][nf][1];
      s [mf*2+1] += acc[mf][nf][2]+acc[mf][nf][3];
      sq[mf*2+1] += acc[mf][nf][2]*acc[mf][nf][2] + acc[mf][nf][3]*acc[mf][nf][3];
    }
  #pragma unroll
  for (int sl=0; sl<4; sl++){
    s [sl] += __shfl_xor_sync(0xffffffffu, s [sl], 1);
    s [sl] += __shfl_xor_sync(0xffffffffu, s [sl], 2);
    sq[sl] += __shfl_xor_sync(0xffffffffu, sq[sl], 1);
    sq[sl] += __shfl_xor_sync(0xffffffffu, sq[sl], 2);
  }
  __syncthreads();
  if (tig == 0){
    #pragma unroll
    for (int sl=0; sl<4; sl++){
      int mf = sl >> 1, h = sl & 1;
      int row = warpM*32 + mf*16 + h*8 + g;
      s_red[row*8 + warpN*2 + 0] = s[sl];
      s_red[row*8 + warpN*2 + 1] = sq[sl];
    }
  }
  __syncthreads();

  float mean_[4], rstd_[4];
  #pragma unroll
  for (int sl=0; sl<4; sl++){
    int mf = sl >> 1, h = sl & 1;
    int row = warpM*32 + mf*16 + h*8 + g;
    float su = s_red[row*8+0]+s_red[row*8+2]+s_red[row*8+4]+s_red[row*8+6];
    float qq = s_red[row*8+1]+s_red[row*8+3]+s_red[row*8+5]+s_red[row*8+7];
    float mn = su * (1.f/HCH);
    float var = qq * (1.f/HCH) - mn*mn;
    mean_[sl] = mn;
    rstd_[sl] = rsqrtf(var + 1e-5f);
  }

  #pragma unroll
  for (int mf=0; mf<2; mf++)
    #pragma unroll
    for (int nf=0; nf<8; nf++){
      int ch0 = warpN*64 + nf*8 + tig*2;
      float g0 = s_g[ch0], g1 = s_g[ch0+1];
      float t0 = s_bt[ch0], t1 = s_bt[ch0+1];
      #pragma unroll
      for (int h=0; h<2; h++){
        int sl = mf*2 + h;
        int row = n0 + warpM*32 + mf*16 + h*8 + g;
        float v0 = (acc[mf][nf][h*2+0] - mean_[sl])*rstd_[sl]*g0 + t0;
        float v1 = (acc[mf][nf][h*2+1] - mean_[sl])*rstd_[sl]*g1 + t1;
        float2 hv = *(const float2*)&hs[(size_t)row*HCH + ch0];
        hv.x += gelu_exact(v0);
        hv.y += gelu_exact(v1);
        *(float2*)&hd[(size_t)row*HCH + ch0] = hv;
      }
    }
}

// ---------------- proj weight prep: bf16 hi/lo, chunked swizzled ----------------
__global__ void k_padw(const float* __restrict__ pjw, const float* __restrict__ pjb){
  int o = blockIdx.x, k = threadIdx.x;
  float w = (o < OUTCH) ? pjw[o*HCH + k] : 0.f;
  __nv_bfloat16 h = __float2bfloat16(w);
  __nv_bfloat16 l = __float2bfloat16(w - __bfloat162float(h));
  int chunk = k >> 6;
  int kk = k & 63;
  int uu = kk >> 3, pos = kk & 7;
  int off = chunk*4096 + o*64 + ((uu ^ (o & 7)) << 3) + pos;
  g_pwh[off] = h;
  g_pwl[off] = l;
  if (k == 0) g_pb[o] = (o < OUTCH) ? pjb[o] : 0.f;
}

// ---------------- projection: bf16 hi/lo mma, reads g_hA ----------------
__global__ void __launch_bounds__(256) k_projmma(const float* __restrict__ mask){
  __shared__ __nv_bfloat16 sAh[64*64], sAl[64*64], sBh[64*64], sBl[64*64];
  __shared__ float s_pb[64];
  int tid = threadIdx.x, lane = tid & 31, wid = tid >> 5;
  int warpM = wid & 3, warpN = wid >> 2;
  int g = lane >> 2, tig = lane & 3;
  int mat = lane >> 3, mr = lane & 7;
  int n0 = blockIdx.x * 64;
  if (tid < 64) s_pb[tid] = g_pb[tid];

  uint32_t sah = smem_u32(sAh), sal = smem_u32(sAl);
  uint32_t sbh = smem_u32(sBh), sbl = smem_u32(sBl);

  float acc[4][4];
  #pragma unroll
  for (int nf=0;nf<4;nf++)
    #pragma unroll
    for (int k=0;k<4;k++) acc[nf][k]=0.f;

  int arow_l = (mat & 1)*8 + mr;   int amh = mat >> 1;
  int brow_l = (mat >> 1)*8 + mr;  int bmh = mat & 1;
  uint32_t aOffW = (uint32_t)((warpM*16 + arow_l)*128);
  uint32_t bOffW = (uint32_t)((warpN*32 + brow_l)*128);

  int row = tid >> 2;
  int kq  = (tid & 3) * 16;
  float m_row = mask[n0 + row];
  int r7 = row & 7;
  int u0 = (tid & 3) * 2;

  for (int chunk=0; chunk<4; chunk++){
    __syncthreads();
    {
      float hv[16];
      const float* src = &g_hA[(size_t)(n0+row)*HCH + chunk*64 + kq];
      *(float4*)&hv[0]  = *(const float4*)&src[0];
      *(float4*)&hv[4]  = *(const float4*)&src[4];
      *(float4*)&hv[8]  = *(const float4*)&src[8];
      *(float4*)&hv[12] = *(const float4*)&src[12];
      __nv_bfloat16 hi[16], lo[16];
      #pragma unroll
      for (int j=0;j<16;j++){
        float v = hv[j]*m_row;
        __nv_bfloat16 h = __float2bfloat16(v);
        hi[j] = h;
        lo[j] = __float2bfloat16(v - __bfloat162float(h));
      }
      uint32_t o0 = (uint32_t)(row*128 + ((u0 ^ r7) << 4));
      uint32_t o1 = (uint32_t)(row*128 + (((u0+1) ^ r7) << 4));
      *(uint4*)((char*)sAh + o0) = *(uint4*)&hi[0];
      *(uint4*)((char*)sAh + o1) = *(uint4*)&hi[8];
      *(uint4*)((char*)sAl + o0) = *(uint4*)&lo[0];
      *(uint4*)((char*)sAl + o1) = *(uint4*)&lo[8];
    }
    {
      const uint4* srcH = (const uint4*)&g_pwh[chunk*4096];
      const uint4* srcL = (const uint4*)&g_pwl[chunk*4096];
      ((uint4*)sBh)[tid]       = srcH[tid];
      ((uint4*)sBh)[tid + 256] = srcH[tid + 256];
      ((uint4*)sBl)[tid]       = srcL[tid];
      ((uint4*)sBl)[tid + 256] = srcL[tid + 256];
    }
    __syncthreads();

    #pragma unroll
    for (int kst=0; kst<4; kst++){
      uint32_t ua = (uint32_t)(((2*kst + amh) ^ mr) << 4);
      uint32_t ub = (uint32_t)(((2*kst + bmh) ^ mr) << 4);
      unsigned ah[4], al[4];
      ldsm4(ah[0],ah[1],ah[2],ah[3], sah + aOffW + ua);
      ldsm4(al[0],al[1],al[2],al[3], sal + aOffW + ua);
      unsigned bh[4][2], bl[4][2];
      #pragma unroll
      for (int np=0; np<2; np++){
        unsigned t0,t1,t2,t3;
        ldsm4(t0,t1,t2,t3, sbh + bOffW + np*2048 + ub);
        bh[2*np][0]=t0; bh[2*np][1]=t1; bh[2*np+1][0]=t2; bh[2*np+1][1]=t3;
        ldsm4(t0,t1,t2,t3, sbl + bOffW + np*2048 + ub);
        bl[2*np][0]=t0; bl[2*np][1]=t1; bl[2*np+1][0]=t2; bl[2*np+1][1]=t3;
      }
      #pragma unroll
      for (int nf=0; nf<4; nf++){
        mma_bf16(acc[nf], ah, bh[nf][0], bh[nf][1]);
        mma_bf16(acc[nf], ah, bl[nf][0], bl[nf][1]);
        mma_bf16(acc[nf], al, bh[nf][0], bh[nf][1]);
      }
    }
  }

  #pragma unroll
  for (int nf=0; nf<4; nf++){
    int ch0 = warpN*32 + nf*8 + tig*2;
    float b0 = s_pb[ch0], b1 = s_pb[ch0+1];
    #pragma unroll
    for (int h=0; h<2; h++){
      int r = n0 + warpM*16 + h*8 + g;
      float m = mask[r];
      float2 v;
      v.x = (acc[nf][h*2+0] + b0) * m;
      v.y = (acc[nf][h*2+1] + b1) * m;
      *(float2*)&g_p[(size_t)r*OPAD + ch0] = v;
    }
  }
}

// ---------------- rational-quadratic spline ----------------
__global__ void k_spline(const float* __restrict__ x, const float* __restrict__ mask,
                         float* __restrict__ out){
  int i = blockIdx.x*256 + threadIdx.x;
  int t = i & (TLEN-1);
  int bc = i >> 12;
  int c = bc & 1, b = bc >> 1;
  float m = mask[b*TLEN + t];
  const float* p = &g_p[(size_t)(b*TLEN + t)*OPAD + c*29];
  float x1 = x[(b*4 + 2 + c)*TLEN + t];

  out[(b*4 + c)*TLEN + t] = x[(b*4 + c)*TLEN + t] * m;

  const float scale = 0.0625f;
  float ew[10], eh[10];
  float mw = -1e30f, mh = -1e30f;
  #pragma unroll
  for (int j=0;j<10;j++){ mw = fmaxf(mw, p[j]*scale); mh = fmaxf(mh, p[10+j]*scale); }
  float sw = 0.f, sh = 0.f;
  #pragma unroll
  for (int j=0;j<10;j++){
    ew[j] = expf(p[j]*scale - mw);    sw += ew[j];
    eh[j] = expf(p[10+j]*scale - mh); sh += eh[j];
  }
  float invsw = 1.f/sw, invsh = 1.f/sh;
  float xc = fminf(fmaxf(x1, -5.f), 5.f);

  float cumw = 0.f, cumh = 0.f;
  float cwj = -5.f, chj = -5.f;
  int idx = 9;
  float in_cw = 0.f, in_w = 1.f, in_ch = 0.f, in_h = 1.f;
  bool found = false;
  #pragma unroll
  for (int j=0;j<10;j++){
    cumw += 0.001f + 0.99f*ew[j]*invsw;
    cumh += 0.001f + 0.99f*eh[j]*invsh;
    float nw = (j==9) ? 5.f : fmaf(10.f, cumw, -5.f);
    float nh = (j==9) ? 5.f : fmaf(10.f, cumh, -5.f);
    if (!found && (xc < nw || j==9)){
      found = true; idx = j;
      in_cw = cwj; in_w = nw - cwj;
      in_ch = chj; in_h = nh - chj;
    }
    cwj = nw; chj = nh;
  }
  float dk  = (idx==0) ? 1.f : 0.001f + softplusf(p[20 + idx - 1]);
  float dk1 = (idx==9) ? 1.f : 0.001f + softplusf(p[20 + idx]);
  float delta = in_h / in_w;
  float th  = (xc - in_cw) / in_w;
  float th2 = th*th;
  float t1m = th*(1.f - th);
  float num = in_h * (delta*th2 + dk*t1m);
  float den = delta + (dk + dk1 - 2.f*delta)*t1m;
  float y = in_ch + num/den;
  float omt = 1.f - th;
  float dnum = delta*delta*(dk1*th2 + 2.f*delta*t1m + dk*omt*omt);
  float lad = logf(dnum) - 2.f*logf(den);

  bool inside = (x1 >= -5.f) && (x1 <= 5.f);
  y   = inside ? y   : x1;
  lad = inside ? lad : 0.f;

  out[(b*4 + 2 + c)*TLEN + t] = y * m;
  g_lad[i] = lad * m;
}

__global__ void k_reduce(float* __restrict__ out){
  int b = blockIdx.x;
  float s = 0.f;
  for (int j = threadIdx.x; j < 2*TLEN; j += 256) s += g_lad[b*2*TLEN + j];
  __shared__ float sm[8];
  #pragma unroll
  for (int o=16;o;o>>=1) s += __shfl_xor_sync(0xffffffffu, s, o);
  if ((threadIdx.x&31)==0) sm[threadIdx.x>>5]=s;
  __syncthreads();
  if (threadIdx.x == 0){
    float r = sm[0]+sm[1]+sm[2]+sm[3]+sm[4]+sm[5]+sm[6]+sm[7];
    out[BATCH*4*TLEN + b] = r;
  }
}

extern "C" void kernel_launch(void* const* d_in, const int* in_sizes, int n_in,
                              void* d_out, int out_size){
  const float* x     = (const float*)d_in[0];
  const float* xm    = (const float*)d_in[1];
  const float* pre_w = (const float*)d_in[2];
  const float* pre_b = (const float*)d_in[3];
  const float* sep_w = (const float*)d_in[4];
  const float* sep_b = (const float*)d_in[5];
  const float* c1w   = (const float*)d_in[6];
  const float* c1b   = (const float*)d_in[7];
  const float* n1g   = (const float*)d_in[8];
  const float* n1b   = (const float*)d_in[9];
  const float* n2g   = (const float*)d_in[10];
  const float* n2b   = (const float*)d_in[11];
  const float* pjw   = (const float*)d_in[12];
  const float* pjb   = (const float*)d_in[13];
  float* out = (float*)d_out;

  static int smem_set = 0;
  if (!smem_set){
    cudaFuncSetAttribute(k_layer, cudaFuncAttributeMaxDynamicSharedMemorySize, GSMEM);
    smem_set = 1;
  }

  k_wprep<<<(LLAYER*HCH*HCH/4)/256, 256>>>(c1w);
  k_padw<<<OPAD, HCH>>>(pjw, pjb);

  int dil = 1;
  for (int i=0;i<LLAYER;i++){
    int srcsel = i & 1;
    k_layer<<<NPOS/64, 256, GSMEM>>>(i, srcsel, dil, x, xm,
        pre_w, pre_b,
        sep_w + i*HCH*3, sep_b + i*HCH,
        n1g + i*HCH, n1b + i*HCH,
        c1b + i*HCH,
        n2g + i*HCH, n2b + i*HCH);
    dil *= 3;
  }

  k_projmma<<<NPOS/64, 256>>>(xm);
  k_spline<<<(BATCH*2*TLEN)/256, 256>>>(x, xm, out);
  k_reduce<<<BATCH, 256>>>(out);
}